// round 3
// baseline (speedup 1.0000x reference)
#include <cuda_runtime.h>

#define BB   64
#define HH   384
#define NPLT 16
#define NG   25
#define CAND 625   // NG*NG
#define LF   400   // HH + NPLT
#define KYC  5     // ky-chunk per k_base block

#define LOG2E_F  1.4426950408889634f
#define LOG2PI_F 1.8378770664093453f

// persistent scratch (allocation-free rule: __device__ globals)
__device__ float g_xlim[NG];
__device__ float g_ylim[NG];
__device__ float g_S[BB * CAND];
__device__ float g_pred[BB * NPLT * 2];
__device__ float g_c2;    // (0.5/sigma^2) * LOG2E
__device__ float g_beta;

__device__ __forceinline__ float ex2f(float x) {
    float r;
    asm("ex2.approx.ftz.f32 %0, %1;" : "=f"(r) : "f"(x));
    return r;
}

// ---------------------------------------------------------------------------
// Kernel 1: base S via separable factorization.
//   S[b][k] = sum_j exp(bt_j - c*dx^2 - c*dy^2)
//           = sum_j Bx[j][kx] * Ay[j][ky],  Bx = exp(bt_j - c*dx^2), Ay = exp(-c*dy^2)
// grid (5 ky-chunks, 64 batches), 128 threads.
// Each block also (redundantly) computes the global grid bounds + constants,
// eliminating the separate setup kernel. Block (0,0) publishes g_xlim/g_ylim/
// g_c2/g_beta for the downstream kernels.
// ---------------------------------------------------------------------------
__global__ void k_base(const float* __restrict__ itime,
                       const float* __restrict__ hist,
                       const float* __restrict__ beta_p,
                       const float* __restrict__ logsig_p) {
    __shared__ float Bx[HH][NG];    // 38400 B
    __shared__ float Ay[HH][KYC];   //  7680 B
    __shared__ float xl[NG], yl[NG];
    __shared__ float bounds[4];

    const int b   = blockIdx.y;
    const int ky0 = blockIdx.x * KYC;
    const int t   = threadIdx.x;

    // ---- global bounds over history points 0 and 1 (all batches, both dims) ----
    float* sc = &Bx[0][0];  // scratch alias (Bx written later)
    {
        int bb = t >> 1, d = t & 1;
        float v0 = hist[bb * (HH * 2) + d];
        float v1 = hist[bb * (HH * 2) + 2 + d];
        sc[t] = v0; __syncthreads();
        for (int o = 64; o; o >>= 1) { if (t < o) sc[t] = fminf(sc[t], sc[t + o]); __syncthreads(); }
        if (t == 0) bounds[0] = sc[0];
        __syncthreads();
        sc[t] = v0; __syncthreads();
        for (int o = 64; o; o >>= 1) { if (t < o) sc[t] = fmaxf(sc[t], sc[t + o]); __syncthreads(); }
        if (t == 0) bounds[1] = sc[0];
        __syncthreads();
        sc[t] = v1; __syncthreads();
        for (int o = 64; o; o >>= 1) { if (t < o) sc[t] = fminf(sc[t], sc[t + o]); __syncthreads(); }
        if (t == 0) bounds[2] = sc[0];
        __syncthreads();
        sc[t] = v1; __syncthreads();
        for (int o = 64; o; o >>= 1) { if (t < o) sc[t] = fmaxf(sc[t], sc[t + o]); __syncthreads(); }
        if (t == 0) bounds[3] = sc[0];
        __syncthreads();
    }

    const float beta = beta_p[0];
    const float sig  = __expf(logsig_p[0]);
    const float c2   = (0.5f / (sig * sig)) * LOG2E_F;

    if (t < NG) {
        float minx = bounds[0], maxx = bounds[1];
        float miny = bounds[2], maxy = bounds[3];
        float fx = (t == NG - 1) ? maxx : minx + (maxx - minx) * ((float)t / (float)(NG - 1));
        float fy = (t == NG - 1) ? maxy : miny + (maxy - miny) * ((float)t / (float)(NG - 1));
        xl[t] = fx; yl[t] = fy;
        if (blockIdx.x == 0 && blockIdx.y == 0) { g_xlim[t] = fx; g_ylim[t] = fy; }
    }
    if (t == 0 && blockIdx.x == 0 && blockIdx.y == 0) { g_c2 = c2; g_beta = beta; }
    __syncthreads();

    // ---- build tables ----
    for (int idx = t; idx < HH * NG; idx += 128) {
        int j = idx / NG, kx = idx - j * NG;
        float sx = hist[b * (HH * 2) + 2 * j];
        float bt = beta * itime[b * HH + j] * LOG2E_F;
        float dx = xl[kx] - sx;
        Bx[j][kx] = ex2f(fmaf(-c2, dx * dx, bt));
    }
    for (int idx = t; idx < HH * KYC; idx += 128) {
        int j = idx / KYC, kl = idx - j * KYC;
        float sy = hist[b * (HH * 2) + 2 * j + 1];
        float dy = yl[ky0 + kl] - sy;
        Ay[j][kl] = ex2f(-c2 * dy * dy);
    }
    __syncthreads();

    // ---- 125 dot products of length 384 ----
    if (t < NG * KYC) {
        int kx = t % NG, kl = t / NG;
        float s = 0.f;
#pragma unroll 8
        for (int j = 0; j < HH; j++)
            s = fmaf(Bx[j][kx], Ay[j][kl], s);
        g_S[b * CAND + (ky0 + kl) * NG + kx] = s;
    }
}

// ---------------------------------------------------------------------------
// Kernel 2: 16-step sequential argmin loop. ONE WARP per batch, zero barriers.
// Each lane owns 20 candidates in registers. argmin(ll) == argmin(S);
// first-index tie-break via packed (float_bits(S)<<32 | idx) min (S >= 0).
// Also initializes out[b] with logp0 + constant terms for k_gmm's atomics.
// ---------------------------------------------------------------------------
__global__ void k_iter(const float* __restrict__ curr,
                       const float* __restrict__ hist,
                       const float* __restrict__ logsig_p,
                       float* __restrict__ out) {
    const int b = blockIdx.x;
    const int lane = threadIdx.x;  // 32
    const float c2 = g_c2, beta = g_beta;

    if (lane == 0) {
        float x0 = hist[b * (HH * 2)];
        float y0 = hist[b * (HH * 2) + 1];
        float ls = logsig_p[0];
        float C = 2.f * ls + LOG2PI_F;
        out[b] = -0.5f * (x0 * x0 + y0 * y0) - LOG2PI_F - (float)(LF - 1) * C;
    }

    const int NR = 20;  // ceil(625/32)
    float s[NR], cx[NR], cy[NR];
#pragma unroll
    for (int r = 0; r < NR; r++) {
        int k = lane + 32 * r;
        if (k < CAND) {
            cx[r] = g_xlim[k % NG];
            cy[r] = g_ylim[k / NG];
            s[r]  = g_S[b * CAND + k];
        } else {
            s[r] = 0.f; cx[r] = 0.f; cy[r] = 0.f;
        }
    }

    for (int i = 0; i < NPLT; i++) {
        unsigned long long best = 0xFFFFFFFFFFFFFFFFULL;
#pragma unroll
        for (int r = 0; r < NR; r++) {
            int k = lane + 32 * r;
            if (k < CAND) {
                unsigned long long key =
                    (((unsigned long long)__float_as_uint(s[r])) << 32) | (unsigned)k;
                best = (key < best) ? key : best;
            }
        }
#pragma unroll
        for (int o = 16; o; o >>= 1) {
            unsigned long long other = __shfl_xor_sync(0xffffffffu, best, o);
            best = (other < best) ? other : best;
        }
        unsigned idx = (unsigned)(best & 0xffffffffu);
        float px = g_xlim[idx % NG];
        float py = g_ylim[idx / NG];

        if (lane == 0) {
            out[BB + (i * BB + b) * 2 + 0] = px;
            out[BB + (i * BB + b) * 2 + 1] = py;
            g_pred[(b * NPLT + i) * 2 + 0] = px;
            g_pred[(b * NPLT + i) * 2 + 1] = py;
        }
        if (i < NPLT - 1) {
            float bt = beta * __ldg(&curr[b * NPLT + i]) * LOG2E_F;
#pragma unroll
            for (int r = 0; r < NR; r++) {
                float dx = cx[r] - px;
                float dy = cy[r] - py;
                float sq = fmaf(dx, dx, dy * dy);
                s[r] += ex2f(fmaf(-c2, sq, bt));
            }
        }
    }
}

// ---------------------------------------------------------------------------
// Kernel 3: final GMM log-likelihood.
//   logp_i = log(sum_{j<i} e_j * g_ij) - log(sum_{j<i} e_j) - C
// with e_j = exp(beta*t_j) precomputed (the exp(-beta*t_i) factor cancels),
// g_ij = exp(-c*sq). Grid (8 chunks, 64 batches), 128 thr, warp-per-row,
// atomicAdd partial sums into out[b] (pre-initialized by k_iter).
// ---------------------------------------------------------------------------
__global__ void k_gmm(const float* __restrict__ itime,
                      const float* __restrict__ hist,
                      const float* __restrict__ curr,
                      float* __restrict__ out) {
    __shared__ float exj[LF], px[LF], py[LF];
    const int b = blockIdx.y;
    const int c = blockIdx.x;   // 8 chunks
    const int t = threadIdx.x;  // 128
    const float beta = g_beta, c2 = g_c2;

    for (int j = t; j < HH; j += 128) {
        px[j]  = hist[b * (HH * 2) + 2 * j];
        py[j]  = hist[b * (HH * 2) + 2 * j + 1];
        exj[j] = ex2f(beta * itime[b * HH + j] * LOG2E_F);
    }
    if (t < NPLT) {
        px[HH + t]  = g_pred[(b * NPLT + t) * 2 + 0];
        py[HH + t]  = g_pred[(b * NPLT + t) * 2 + 1];
        exj[HH + t] = ex2f(beta * curr[b * NPLT + t] * LOG2E_F);
    }
    __syncthreads();

    const int w = t >> 5, lane = t & 31;
    float acc = 0.f;

    for (int i = 1 + c * 4 + w; i < LF; i += 32) {
        float xi = px[i], yi = py[i];
        float s1 = 0.f, s2 = 0.f;
        for (int j = lane; j < i; j += 32) {
            float e = exj[j];
            float dx = xi - px[j];
            float dy = yi - py[j];
            float sq = fmaf(dx, dx, dy * dy);
            s1 += e;
            s2 = fmaf(e, ex2f(-c2 * sq), s2);
        }
#pragma unroll
        for (int o = 16; o; o >>= 1) {
            s1 += __shfl_down_sync(0xffffffffu, s1, o);
            s2 += __shfl_down_sync(0xffffffffu, s2, o);
        }
        if (lane == 0) acc += logf(s2) - logf(s1);
    }
    if (lane == 0) atomicAdd(&out[b], acc);
}

// ---------------------------------------------------------------------------
extern "C" void kernel_launch(void* const* d_in, const int* in_sizes, int n_in,
                              void* d_out, int out_size) {
    const float* curr   = (const float*)d_in[0];  // (64,16)
    const float* itime  = (const float*)d_in[1];  // (64,384)
    const float* hist   = (const float*)d_in[2];  // (64,384,2)
    // d_in[3..5] (expected_data, aux_*) are dead inputs
    const float* beta   = (const float*)d_in[6];
    const float* logsig = (const float*)d_in[7];
    float* out = (float*)d_out;  // [64 loglik][16*64*2 predicted]

    k_base<<<dim3(5, BB), 128>>>(itime, hist, beta, logsig);
    k_iter<<<BB, 32>>>(curr, hist, logsig, out);
    k_gmm<<<dim3(8, BB), 128>>>(itime, hist, curr, out);
}